// round 12
// baseline (speedup 1.0000x reference)
#include <cuda_runtime.h>
#include <cstdint>

#define HID   128
#define NEDGE 800000
#define NNODE 50000
#define NTILE 6250          // NEDGE / 128
#define NTILEN 391          // ceil(NNODE / 128)
#define GRID_E 444          // 3 CTAs/SM * 148 SMs
#define EBS 80              // bf16x2 words per edge row (mod 32 == 16 -> LDS.128 conflict-free)
#define DS  132             // sD stride in floats
#define HBS 140             // tf32 words per node row in node_mma

// ---- scratch (static __device__ arrays; allocation-free) ----
__device__ float g_Ha[NNODE * HID];
__device__ float g_Hb[NNODE * HID];
__device__ float g_a[NEDGE];
__device__ int   g_row[NEDGE];
__device__ int   g_col[NEDGE];
__device__ int   g_is64;
__device__ float g_pm[512];
__device__ float g_ps[512];
__device__ float g_stats[2];
__device__ uint4 g_Af[64 * 32];          // bf16 A frags for edge_mma [wid][K16][lane]
__device__ uint4 g_Wab[2 * 8 * 16 * 32]; // tf32 A frags for node_mma [slice][wid][K8][lane]

// ---- helpers ----
__device__ __forceinline__ uint32_t pk_bf(float lo, float hi) {
    uint32_t r;   // cvt.bf16x2: first src -> upper half
    asm("cvt.rn.bf16x2.f32 %0, %1, %2;" : "=r"(r) : "f"(hi), "f"(lo));
    return r;
}
__device__ __forceinline__ uint32_t f2tf32(float x) {
    uint32_t u;
    asm("cvt.rna.tf32.f32 %0, %1;" : "=r"(u) : "f"(x));
    return u;
}
__device__ __forceinline__ void mma_bf(float* c, const uint4& a, uint32_t b0, uint32_t b1) {
    asm volatile(
        "mma.sync.aligned.m16n8k16.row.col.f32.bf16.bf16.f32 "
        "{%0,%1,%2,%3}, {%4,%5,%6,%7}, {%8,%9}, {%0,%1,%2,%3};"
        : "+f"(c[0]), "+f"(c[1]), "+f"(c[2]), "+f"(c[3])
        : "r"(a.x), "r"(a.y), "r"(a.z), "r"(a.w), "r"(b0), "r"(b1));
}
__device__ __forceinline__ void mma_tf(float* c, const uint4& a, uint32_t b0, uint32_t b1) {
    asm volatile(
        "mma.sync.aligned.m16n8k8.row.col.f32.tf32.tf32.f32 "
        "{%0,%1,%2,%3}, {%4,%5,%6,%7}, {%8,%9}, {%0,%1,%2,%3};"
        : "+f"(c[0]), "+f"(c[1]), "+f"(c[2]), "+f"(c[3])
        : "r"(a.x), "r"(a.y), "r"(a.z), "r"(a.w), "r"(b0), "r"(b1));
}
__device__ __forceinline__ float elu(float x) {
    return x > 0.f ? x : (__expf(x) - 1.f);
}
__device__ __forceinline__ void merge_ms(float& m, float& s, float m2, float s2) {
    float mn = fmaxf(m, m2);
    s = s * __expf(m - mn) + s2 * __expf(m2 - mn);
    m = mn;
}

// ============================================================
// Kernel 0a/0b: edge_index dtype detect + convert
// ============================================================
__global__ void detect(const int* __restrict__ ei32) {
    if (threadIdx.x == 0 && blockIdx.x == 0) {
        int orv = 0;
        for (int i = 0; i < 64; i++) orv |= ei32[2 * i + 1];
        g_is64 = (orv == 0) ? 1 : 0;
    }
}
__global__ void __launch_bounds__(256) convert(const void* __restrict__ eiraw) {
    int e = blockIdx.x * 256 + threadIdx.x;
    if (e >= NEDGE) return;
    int row, col;
    if (g_is64) {
        const long long* p = (const long long*)eiraw;
        row = (int)p[e]; col = (int)p[NEDGE + e];
    } else {
        const int* p = (const int*)eiraw;
        row = p[e]; col = p[NEDGE + e];
    }
    g_row[e] = min(max(row, 0), NNODE - 1);
    g_col[e] = min(max(col, 0), NNODE - 1);
}

// ============================================================
// Kernel 0c: pre-pack Wc into bf16 A-fragments (edge_mma)
// ============================================================
__global__ void __launch_bounds__(256) prep_afrag(const float* __restrict__ W1) {
    int t = blockIdx.x * 256 + threadIdx.x;   // 0..2047
    int lane = t & 31, K16 = (t >> 5) & 7, wid = t >> 8;
    int tg = lane >> 2, tk = lane & 3;
    int o0 = 16 * wid + tg;
    int kb = K16 * 16 + 2 * tk;
    const float* Wc = W1 + 2 * HID * HID;
    uint4 r;
    r.x = pk_bf(Wc[kb * HID + o0],           Wc[(kb + 1) * HID + o0]);
    r.y = pk_bf(Wc[kb * HID + o0 + 8],       Wc[(kb + 1) * HID + o0 + 8]);
    r.z = pk_bf(Wc[(kb + 8) * HID + o0],     Wc[(kb + 9) * HID + o0]);
    r.w = pk_bf(Wc[(kb + 8) * HID + o0 + 8], Wc[(kb + 9) * HID + o0 + 8]);
    g_Af[t] = r;
}

// ============================================================
// Kernel 0d: pre-pack Wa|Wb into tf32 A-fragments (node_mma)
// ============================================================
__global__ void __launch_bounds__(256) prep_wab(const float* __restrict__ W1) {
    int t = blockIdx.x * 256 + threadIdx.x;   // 0..8191
    int lane = t & 31, K8 = (t >> 5) & 15, wid = (t >> 9) & 7, s = t >> 12;
    int tg = lane >> 2, tk = lane & 3;
    int o0 = 16 * wid + tg;
    int kb = K8 * 8;
    const float* Wb_ = W1 + (size_t)s * HID * HID;
    uint4 r;
    r.x = f2tf32(Wb_[(kb + tk) * HID + o0]);
    r.y = f2tf32(Wb_[(kb + tk) * HID + o0 + 8]);
    r.z = f2tf32(Wb_[(kb + tk + 4) * HID + o0]);
    r.w = f2tf32(Wb_[(kb + tk + 4) * HID + o0 + 8]);
    g_Wab[t] = r;
}

// ============================================================
// Kernel 1: node GEMM via mma.sync tf32  ->  Ha | Hb
// ============================================================
__global__ void __launch_bounds__(256, 2) node_mma(const float* __restrict__ h) {
    extern __shared__ uint32_t eb[];           // [128][HBS]
    int tid = threadIdx.x, wid = tid >> 5, lane = tid & 31;
    int tg = lane >> 2, tk = lane & 3;
    int o0 = 16 * wid + tg, o1 = o0 + 8;
    int nbase = blockIdx.x * 128;

    const float4* src = (const float4*)(h + (size_t)nbase * HID);
#pragma unroll
    for (int pass = 0; pass < 8; pass++) {
        int flat8 = pass * 256 + tid;
        int r = flat8 >> 4, kb = flat8 & 15;
        float4 v0 = make_float4(0.f, 0.f, 0.f, 0.f), v1 = v0;
        if (nbase + r < NNODE) {
            v0 = src[flat8 * 2];
            v1 = src[flat8 * 2 + 1];
        }
        uint4 q0, q1;
        q0.x = f2tf32(v0.x); q0.y = f2tf32(v1.x);
        q0.z = f2tf32(v0.y); q0.w = f2tf32(v1.y);
        q1.x = f2tf32(v0.z); q1.y = f2tf32(v1.z);
        q1.z = f2tf32(v0.w); q1.w = f2tf32(v1.w);
        uint32_t* drow = eb + r * HBS + kb * 8;
        *(uint4*)(drow)     = q0;
        *(uint4*)(drow + 4) = q1;
    }
    __syncthreads();

#pragma unroll
    for (int slab = 0; slab < 2; slab++) {
        float c0[8][4], c1[8][4];
#pragma unroll
        for (int g = 0; g < 8; g++) {
            c0[g][0]=0.f; c0[g][1]=0.f; c0[g][2]=0.f; c0[g][3]=0.f;
            c1[g][0]=0.f; c1[g][1]=0.f; c1[g][2]=0.f; c1[g][3]=0.f;
        }
        const uint32_t* ebp = eb + slab * 64 * HBS;
#pragma unroll
        for (int K8 = 0; K8 < 16; K8++) {
            uint4 a0 = g_Wab[(wid * 16 + K8) * 32 + lane];
            uint4 a1 = g_Wab[4096 + (wid * 16 + K8) * 32 + lane];
#pragma unroll
            for (int g = 0; g < 8; g++) {
                uint2 b = *(const uint2*)(ebp + (g * 8 + tg) * HBS + K8 * 8 + 2 * tk);
                mma_tf(c0[g], a0, b.x, b.y);
                mma_tf(c1[g], a1, b.x, b.y);
            }
        }
#pragma unroll
        for (int g = 0; g < 8; g++) {
            int node = nbase + slab * 64 + g * 8 + 2 * tk;
            if (node < NNODE) {
                g_Ha[(size_t)node * HID + o0] = c0[g][0];
                g_Ha[(size_t)node * HID + o1] = c0[g][2];
                g_Hb[(size_t)node * HID + o0] = c1[g][0];
                g_Hb[(size_t)node * HID + o1] = c1[g][2];
            }
            if (node + 1 < NNODE) {
                g_Ha[(size_t)(node + 1) * HID + o0] = c0[g][1];
                g_Ha[(size_t)(node + 1) * HID + o1] = c0[g][3];
                g_Hb[(size_t)(node + 1) * HID + o0] = c1[g][1];
                g_Hb[(size_t)(node + 1) * HID + o1] = c1[g][3];
            }
        }
    }
}

// ============================================================
// Kernel 2: edge GEMM (bf16 mma, K32-paired LDS.128 B loads)
//   + coalesced epilogue + fused softmax stage-1 partials.
//   smem: eb [128][80]w 40960 | sD [64][132]f 33792 | idx u16 512
//         | b1s 512 | w2s 512  = 76288 B  (3 CTAs/SM)
// ============================================================
__global__ void __launch_bounds__(256, 3) edge_mma(const float* __restrict__ ea,
                                                   const float* __restrict__ b1,
                                                   const float* __restrict__ W2,
                                                   const float* __restrict__ b2) {
    extern __shared__ char sm[];
    uint32_t*       eb   = (uint32_t*)sm;            // [128][80]
    float*          sD   = (float*)(sm + 40960);     // [64][132]
    unsigned short* idxs = (unsigned short*)(sm + 74752);  // [256]
    float*          b1s  = (float*)(sm + 75264);
    float*          w2s  = (float*)(sm + 75776);

    int tid = threadIdx.x, wid = tid >> 5, lane = tid & 31;
    int tg = lane >> 2, tk = lane & 3;
    int o0 = 16 * wid + tg, o1 = o0 + 8;
    float b2v = b2[0];
    float lm = -1e30f, ls = 0.f;          // per-thread softmax partial (lane0 only)

    if (tid < 128) { b1s[tid] = b1[tid]; w2s[tid] = W2[tid]; }

    for (int tile = blockIdx.x; tile < NTILE; tile += GRID_E) {
        int e_ = tid & 127;
        idxs[tid] = (unsigned short)((tid < 128) ? g_row[tile * 128 + e_]
                                                 : g_col[tile * 128 + e_]);
        const float4* src = (const float4*)(ea + (size_t)tile * 128 * HID);
#pragma unroll
        for (int pass = 0; pass < 8; pass++) {
            int flat8 = pass * 256 + tid;          // 8-float chunk (0..2047)
            int r = flat8 >> 4, kb = flat8 & 15;
            float4 v0 = src[flat8 * 2];
            float4 v1 = src[flat8 * 2 + 1];
            // word offset = K32*16 + (kb&3) + 4t  (t=0..3)
            uint32_t* dr = eb + r * EBS + (kb >> 2) * 16 + (kb & 3);
            dr[0]  = pk_bf(v0.x, v0.y);
            dr[4]  = pk_bf(v0.z, v0.w);
            dr[8]  = pk_bf(v1.x, v1.y);
            dr[12] = pk_bf(v1.z, v1.w);
        }
        __syncthreads();

#pragma unroll
        for (int slab = 0; slab < 2; slab++) {
            float c[8][4];
#pragma unroll
            for (int g = 0; g < 8; g++) { c[g][0]=0.f; c[g][1]=0.f; c[g][2]=0.f; c[g][3]=0.f; }
            const uint32_t* ebp = eb + slab * 64 * EBS;
#pragma unroll
            for (int K32 = 0; K32 < 4; K32++) {
                uint4 af0 = g_Af[(wid * 8 + 2 * K32) * 32 + lane];
                uint4 af1 = g_Af[(wid * 8 + 2 * K32 + 1) * 32 + lane];
#pragma unroll
                for (int g = 0; g < 8; g++) {
                    uint4 b = *(const uint4*)(ebp + (g * 8 + tg) * EBS + K32 * 16 + 4 * tk);
                    mma_bf(c[g], af0, b.x, b.y);
                    mma_bf(c[g], af1, b.z, b.w);
                }
            }
#pragma unroll
            for (int g = 0; g < 8; g++) {
                int el = g * 8 + 2 * tk;
                sD[el * DS + o0]       = c[g][0];
                sD[(el + 1) * DS + o0] = c[g][1];
                sD[el * DS + o1]       = c[g][2];
                sD[(el + 1) * DS + o1] = c[g][3];
            }
            __syncthreads();

#pragma unroll
            for (int i = 0; i < 8; i++) {
                int el = wid * 8 + i;
                int e = slab * 64 + el;
                int row = idxs[e], col = idxs[128 + e];
                float4 d   = *(float4*)&sD[el * DS + 4 * lane];
                float4 ha  = *(const float4*)&g_Ha[(size_t)row * HID + 4 * lane];
                float4 hb  = *(const float4*)&g_Hb[(size_t)col * HID + 4 * lane];
                float4 b1v = *(const float4*)&b1s[4 * lane];
                float4 w2v = *(const float4*)&w2s[4 * lane];
                float partial =
                    elu(d.x + ha.x + hb.x + b1v.x) * w2v.x +
                    elu(d.y + ha.y + hb.y + b1v.y) * w2v.y +
                    elu(d.z + ha.z + hb.z + b1v.z) * w2v.z +
                    elu(d.w + ha.w + hb.w + b1v.w) * w2v.w;
#pragma unroll
                for (int off = 16; off; off >>= 1)
                    partial += __shfl_xor_sync(0xffffffffu, partial, off);
                if (lane == 0) {
                    float a = partial + b2v;
                    float lg = a > 0.f ? a : 0.2f * a;
                    g_a[tile * 128 + e] = lg;
                    if (lg > lm) { ls = ls * __expf(lm - lg) + 1.f; lm = lg; }
                    else         { ls += __expf(lg - lm); }
                }
            }
            __syncthreads();
        }
    }

    // ---- block-reduce softmax partials -> g_pm/g_ps[blockIdx] ----
    float* red = (float*)idxs;   // 16 floats, idx space no longer needed
    if (lane == 0) { red[wid] = lm; red[8 + wid] = ls; }
    __syncthreads();
    if (tid == 0) {
        float M = -1e30f, S = 0.f;
#pragma unroll
        for (int w = 0; w < 8; w++) merge_ms(M, S, red[w], red[8 + w]);
        g_pm[blockIdx.x] = M;
        g_ps[blockIdx.x] = S;
    }
}

// ============================================================
// Kernel 3: final softmax reduction over GRID_E partials
// ============================================================
__global__ void softmax_final() {
    int t = threadIdx.x;
    __shared__ float sm_[512], ss_[512];
    float m = -1e30f, s = 0.f;
    if (t < GRID_E) { m = g_pm[t]; s = g_ps[t]; }
    sm_[t] = m; ss_[t] = s;
    __syncthreads();
    for (int off = 256; off; off >>= 1) {
        if (t < off) {
            float mm = sm_[t], ssv = ss_[t];
            merge_ms(mm, ssv, sm_[t + off], ss_[t + off]);
            sm_[t] = mm; ss_[t] = ssv;
        }
        __syncthreads();
    }
    if (t == 0) { g_stats[0] = sm_[0]; g_stats[1] = 1.f / ss_[0]; }
}

// ============================================================
// Kernel 4: scatter  out[row] += alpha_e * h[col]   (red.v4.f32)
// ============================================================
__global__ void __launch_bounds__(256) scatter(const float* __restrict__ h,
                                               float* __restrict__ out) {
    int gw = (blockIdx.x * 256 + threadIdx.x) >> 5;
    int l = threadIdx.x & 31;
    float m = g_stats[0], inv = g_stats[1];
    int e0 = gw * 4;
#pragma unroll
    for (int e = 0; e < 4; e++) {
        int ed = e0 + e;
        if (ed >= NEDGE) return;
        float alpha = __expf(g_a[ed] - m) * inv;
        int row = g_row[ed];
        int col = g_col[ed];
        float4 hv = *(const float4*)&h[(size_t)col * HID + 4 * l];
        float* dst = &out[(size_t)row * HID + 4 * l];
        asm volatile("red.global.add.v4.f32 [%0], {%1, %2, %3, %4};"
                     :: "l"(dst), "f"(alpha * hv.x), "f"(alpha * hv.y),
                        "f"(alpha * hv.z), "f"(alpha * hv.w)
                     : "memory");
    }
}

// ============================================================
extern "C" void kernel_launch(void* const* d_in, const int* in_sizes, int n_in,
                              void* d_out, int out_size) {
    const float* h  = (const float*)d_in[0];
    const void*  ei = (const void*)d_in[1];
    const float* ea = (const float*)d_in[2];
    const float* W1 = (const float*)d_in[3];
    const float* b1 = (const float*)d_in[4];
    const float* W2 = (const float*)d_in[5];
    const float* b2 = (const float*)d_in[6];
    float* out = (float*)d_out;

    // static streams/events: created once on the (non-captured) correctness
    // call; reused identically on every call (same work every time).
    static cudaStream_t sB = nullptr, sC = nullptr;
    static cudaEvent_t evRoot = nullptr, evB = nullptr, evC = nullptr;
    if (sB == nullptr) {
        cudaStreamCreateWithFlags(&sB, cudaStreamNonBlocking);
        cudaStreamCreateWithFlags(&sC, cudaStreamNonBlocking);
        cudaEventCreateWithFlags(&evRoot, cudaEventDisableTiming);
        cudaEventCreateWithFlags(&evB, cudaEventDisableTiming);
        cudaEventCreateWithFlags(&evC, cudaEventDisableTiming);
    }

    cudaFuncSetAttribute(node_mma, cudaFuncAttributeMaxDynamicSharedMemorySize, 71680);
    cudaFuncSetAttribute(edge_mma, cudaFuncAttributeMaxDynamicSharedMemorySize, 76288);

    // fork
    cudaEventRecord(evRoot, 0);
    cudaStreamWaitEvent(sB, evRoot, 0);
    cudaStreamWaitEvent(sC, evRoot, 0);

    // branch A (main stream): edge-index path
    detect<<<1, 32>>>((const int*)ei);
    convert<<<(NEDGE + 255) / 256, 256>>>(ei);
    prep_afrag<<<8, 256>>>(W1);

    // branch B: node path
    prep_wab<<<32, 256, 0, sB>>>(W1);
    node_mma<<<NTILEN, 256, 71680, sB>>>(h);

    // branch C: clear output
    cudaMemsetAsync(d_out, 0, (size_t)out_size * sizeof(float), sC);

    // join B before edge_mma
    cudaEventRecord(evB, sB);
    cudaStreamWaitEvent(0, evB, 0);

    edge_mma<<<GRID_E, 256, 76288>>>(ea, b1, W2, b2);
    softmax_final<<<1, 512>>>();

    // join C before scatter
    cudaEventRecord(evC, sC);
    cudaStreamWaitEvent(0, evC, 0);

    scatter<<<25000, 256>>>(h, out);
}

// round 14
// speedup vs baseline: 1.0474x; 1.0474x over previous
#include <cuda_runtime.h>
#include <cstdint>

#define HID   128
#define NEDGE 800000
#define NNODE 50000
#define NTILE 6250          // NEDGE / 128
#define NTILEN 391          // ceil(NNODE / 128)
#define GRID_E 444          // 3 CTAs/SM * 148 SMs
#define EBS 80              // bf16x2 words per edge row (mod 32 == 16 -> LDS.128 conflict-free)
#define DS  132             // sD stride in floats
#define HBS 140             // tf32 words per node row in node_mma

// ---- scratch (static __device__ arrays; allocation-free) ----
__device__ unsigned short g_Ha16[NNODE * HID];   // h @ Wa, bf16 (12.8 MB)
__device__ unsigned short g_Hb16[NNODE * HID];   // h @ Wb, bf16
__device__ float g_a[NEDGE];
__device__ int   g_row[NEDGE];
__device__ int   g_col[NEDGE];
__device__ int   g_is64;
__device__ float g_ps[512];
__device__ float g_stats[2];
__device__ uint4 g_Af[64 * 32];          // bf16 A frags for edge_mma [wid][K16][lane]
__device__ uint4 g_Wab[2 * 8 * 16 * 32]; // tf32 A frags for node_mma [slice][wid][K8][lane]

// ---- helpers ----
__device__ __forceinline__ uint32_t pk_bf(float lo, float hi) {
    uint32_t r;   // cvt.bf16x2: first src -> upper half
    asm("cvt.rn.bf16x2.f32 %0, %1, %2;" : "=r"(r) : "f"(hi), "f"(lo));
    return r;
}
__device__ __forceinline__ unsigned short f2bf(float x) {
    return (unsigned short)(pk_bf(x, x) & 0xffffu);
}
__device__ __forceinline__ uint32_t f2tf32(float x) {
    uint32_t u;
    asm("cvt.rna.tf32.f32 %0, %1;" : "=r"(u) : "f"(x));
    return u;
}
__device__ __forceinline__ void mma_bf(float* c, const uint4& a, uint32_t b0, uint32_t b1) {
    asm volatile(
        "mma.sync.aligned.m16n8k16.row.col.f32.bf16.bf16.f32 "
        "{%0,%1,%2,%3}, {%4,%5,%6,%7}, {%8,%9}, {%0,%1,%2,%3};"
        : "+f"(c[0]), "+f"(c[1]), "+f"(c[2]), "+f"(c[3])
        : "r"(a.x), "r"(a.y), "r"(a.z), "r"(a.w), "r"(b0), "r"(b1));
}
__device__ __forceinline__ void mma_tf(float* c, const uint4& a, uint32_t b0, uint32_t b1) {
    asm volatile(
        "mma.sync.aligned.m16n8k8.row.col.f32.tf32.tf32.f32 "
        "{%0,%1,%2,%3}, {%4,%5,%6,%7}, {%8,%9}, {%0,%1,%2,%3};"
        : "+f"(c[0]), "+f"(c[1]), "+f"(c[2]), "+f"(c[3])
        : "r"(a.x), "r"(a.y), "r"(a.z), "r"(a.w), "r"(b0), "r"(b1));
}
__device__ __forceinline__ float elu(float x) {
    return x > 0.f ? x : (__expf(x) - 1.f);
}

// ============================================================
// Kernel 0a/0b: edge_index dtype detect + convert
// ============================================================
__global__ void detect(const int* __restrict__ ei32) {
    if (threadIdx.x == 0 && blockIdx.x == 0) {
        int orv = 0;
        for (int i = 0; i < 64; i++) orv |= ei32[2 * i + 1];
        g_is64 = (orv == 0) ? 1 : 0;
    }
}
__global__ void __launch_bounds__(256) convert(const void* __restrict__ eiraw) {
    int e = blockIdx.x * 256 + threadIdx.x;
    if (e >= NEDGE) return;
    int row, col;
    if (g_is64) {
        const long long* p = (const long long*)eiraw;
        row = (int)p[e]; col = (int)p[NEDGE + e];
    } else {
        const int* p = (const int*)eiraw;
        row = p[e]; col = p[NEDGE + e];
    }
    g_row[e] = min(max(row, 0), NNODE - 1);
    g_col[e] = min(max(col, 0), NNODE - 1);
}

// ============================================================
// Kernel 0c: pre-pack Wc into bf16 A-fragments (edge_mma)
// ============================================================
__global__ void __launch_bounds__(256) prep_afrag(const float* __restrict__ W1) {
    int t = blockIdx.x * 256 + threadIdx.x;   // 0..2047
    int lane = t & 31, K16 = (t >> 5) & 7, wid = t >> 8;
    int tg = lane >> 2, tk = lane & 3;
    int o0 = 16 * wid + tg;
    int kb = K16 * 16 + 2 * tk;
    const float* Wc = W1 + 2 * HID * HID;
    uint4 r;
    r.x = pk_bf(Wc[kb * HID + o0],           Wc[(kb + 1) * HID + o0]);
    r.y = pk_bf(Wc[kb * HID + o0 + 8],       Wc[(kb + 1) * HID + o0 + 8]);
    r.z = pk_bf(Wc[(kb + 8) * HID + o0],     Wc[(kb + 9) * HID + o0]);
    r.w = pk_bf(Wc[(kb + 8) * HID + o0 + 8], Wc[(kb + 9) * HID + o0 + 8]);
    g_Af[t] = r;
}

// ============================================================
// Kernel 0d: pre-pack Wa|Wb into tf32 A-fragments (node_mma)
// ============================================================
__global__ void __launch_bounds__(256) prep_wab(const float* __restrict__ W1) {
    int t = blockIdx.x * 256 + threadIdx.x;   // 0..8191
    int lane = t & 31, K8 = (t >> 5) & 15, wid = (t >> 9) & 7, s = t >> 12;
    int tg = lane >> 2, tk = lane & 3;
    int o0 = 16 * wid + tg;
    int kb = K8 * 8;
    const float* Wb_ = W1 + (size_t)s * HID * HID;
    uint4 r;
    r.x = f2tf32(Wb_[(kb + tk) * HID + o0]);
    r.y = f2tf32(Wb_[(kb + tk) * HID + o0 + 8]);
    r.z = f2tf32(Wb_[(kb + tk + 4) * HID + o0]);
    r.w = f2tf32(Wb_[(kb + tk + 4) * HID + o0 + 8]);
    g_Wab[t] = r;
}

// ============================================================
// Kernel 1: node GEMM via mma.sync tf32  ->  Ha | Hb (bf16 out)
// ============================================================
__global__ void __launch_bounds__(256, 2) node_mma(const float* __restrict__ h) {
    extern __shared__ uint32_t eb[];           // [128][HBS]
    int tid = threadIdx.x, wid = tid >> 5, lane = tid & 31;
    int tg = lane >> 2, tk = lane & 3;
    int o0 = 16 * wid + tg, o1 = o0 + 8;
    int nbase = blockIdx.x * 128;

    const float4* src = (const float4*)(h + (size_t)nbase * HID);
#pragma unroll
    for (int pass = 0; pass < 8; pass++) {
        int flat8 = pass * 256 + tid;
        int r = flat8 >> 4, kb = flat8 & 15;
        float4 v0 = make_float4(0.f, 0.f, 0.f, 0.f), v1 = v0;
        if (nbase + r < NNODE) {
            v0 = src[flat8 * 2];
            v1 = src[flat8 * 2 + 1];
        }
        uint4 q0, q1;
        q0.x = f2tf32(v0.x); q0.y = f2tf32(v1.x);
        q0.z = f2tf32(v0.y); q0.w = f2tf32(v1.y);
        q1.x = f2tf32(v0.z); q1.y = f2tf32(v1.z);
        q1.z = f2tf32(v0.w); q1.w = f2tf32(v1.w);
        uint32_t* drow = eb + r * HBS + kb * 8;
        *(uint4*)(drow)     = q0;
        *(uint4*)(drow + 4) = q1;
    }
    __syncthreads();

#pragma unroll
    for (int slab = 0; slab < 2; slab++) {
        float c0[8][4], c1[8][4];
#pragma unroll
        for (int g = 0; g < 8; g++) {
            c0[g][0]=0.f; c0[g][1]=0.f; c0[g][2]=0.f; c0[g][3]=0.f;
            c1[g][0]=0.f; c1[g][1]=0.f; c1[g][2]=0.f; c1[g][3]=0.f;
        }
        const uint32_t* ebp = eb + slab * 64 * HBS;
#pragma unroll
        for (int K8 = 0; K8 < 16; K8++) {
            uint4 a0 = g_Wab[(wid * 16 + K8) * 32 + lane];
            uint4 a1 = g_Wab[4096 + (wid * 16 + K8) * 32 + lane];
#pragma unroll
            for (int g = 0; g < 8; g++) {
                uint2 b = *(const uint2*)(ebp + (g * 8 + tg) * HBS + K8 * 8 + 2 * tk);
                mma_tf(c0[g], a0, b.x, b.y);
                mma_tf(c1[g], a1, b.x, b.y);
            }
        }
#pragma unroll
        for (int g = 0; g < 8; g++) {
            int node = nbase + slab * 64 + g * 8 + 2 * tk;
            if (node < NNODE) {
                g_Ha16[(size_t)node * HID + o0] = f2bf(c0[g][0]);
                g_Ha16[(size_t)node * HID + o1] = f2bf(c0[g][2]);
                g_Hb16[(size_t)node * HID + o0] = f2bf(c1[g][0]);
                g_Hb16[(size_t)node * HID + o1] = f2bf(c1[g][2]);
            }
            if (node + 1 < NNODE) {
                g_Ha16[(size_t)(node + 1) * HID + o0] = f2bf(c0[g][1]);
                g_Ha16[(size_t)(node + 1) * HID + o1] = f2bf(c0[g][3]);
                g_Hb16[(size_t)(node + 1) * HID + o0] = f2bf(c1[g][1]);
                g_Hb16[(size_t)(node + 1) * HID + o1] = f2bf(c1[g][3]);
            }
        }
    }
}

// ============================================================
// Kernel 2: edge GEMM (bf16 mma, K32-paired LDS.128 B loads)
//   + coalesced epilogue (bf16 Ha/Hb gathers) + fused exp-sum.
//   smem: eb [128][80]w 40960 | sD [64][132]f 33792 | idx u16 512
//         | b1s 512 | w2s 512  = 76288 B  (3 CTAs/SM)
// ============================================================
__global__ void __launch_bounds__(256, 3) edge_mma(const float* __restrict__ ea,
                                                   const float* __restrict__ b1,
                                                   const float* __restrict__ W2,
                                                   const float* __restrict__ b2) {
    extern __shared__ char sm[];
    uint32_t*       eb   = (uint32_t*)sm;            // [128][80]
    float*          sD   = (float*)(sm + 40960);     // [64][132]
    unsigned short* idxs = (unsigned short*)(sm + 74752);  // [256]
    float*          b1s  = (float*)(sm + 75264);
    float*          w2s  = (float*)(sm + 75776);

    int tid = threadIdx.x, wid = tid >> 5, lane = tid & 31;
    int tg = lane >> 2, tk = lane & 3;
    int o0 = 16 * wid + tg, o1 = o0 + 8;
    float b2v = b2[0];
    float ls = 0.f;                        // exp-sum partial (identical in all lanes)

    if (tid < 128) { b1s[tid] = b1[tid]; w2s[tid] = W2[tid]; }

    for (int tile = blockIdx.x; tile < NTILE; tile += GRID_E) {
        int e_ = tid & 127;
        idxs[tid] = (unsigned short)((tid < 128) ? g_row[tile * 128 + e_]
                                                 : g_col[tile * 128 + e_]);
        const float4* src = (const float4*)(ea + (size_t)tile * 128 * HID);
#pragma unroll
        for (int pass = 0; pass < 8; pass++) {
            int flat8 = pass * 256 + tid;          // 8-float chunk (0..2047)
            int r = flat8 >> 4, kb = flat8 & 15;
            float4 v0 = src[flat8 * 2];
            float4 v1 = src[flat8 * 2 + 1];
            uint32_t* dr = eb + r * EBS + (kb >> 2) * 16 + (kb & 3);
            dr[0]  = pk_bf(v0.x, v0.y);
            dr[4]  = pk_bf(v0.z, v0.w);
            dr[8]  = pk_bf(v1.x, v1.y);
            dr[12] = pk_bf(v1.z, v1.w);
        }
        __syncthreads();

#pragma unroll
        for (int slab = 0; slab < 2; slab++) {
            float c[8][4];
#pragma unroll
            for (int g = 0; g < 8; g++) { c[g][0]=0.f; c[g][1]=0.f; c[g][2]=0.f; c[g][3]=0.f; }
            const uint32_t* ebp = eb + slab * 64 * EBS;
#pragma unroll
            for (int K32 = 0; K32 < 4; K32++) {
                uint4 af0 = g_Af[(wid * 8 + 2 * K32) * 32 + lane];
                uint4 af1 = g_Af[(wid * 8 + 2 * K32 + 1) * 32 + lane];
#pragma unroll
                for (int g = 0; g < 8; g++) {
                    uint4 b = *(const uint4*)(ebp + (g * 8 + tg) * EBS + K32 * 16 + 4 * tk);
                    mma_bf(c[g], af0, b.x, b.y);
                    mma_bf(c[g], af1, b.z, b.w);
                }
            }
#pragma unroll
            for (int g = 0; g < 8; g++) {
                int el = g * 8 + 2 * tk;
                sD[el * DS + o0]       = c[g][0];
                sD[(el + 1) * DS + o0] = c[g][1];
                sD[el * DS + o1]       = c[g][2];
                sD[(el + 1) * DS + o1] = c[g][3];
            }
            __syncthreads();

#pragma unroll
            for (int i = 0; i < 8; i++) {
                int el = wid * 8 + i;
                int e = slab * 64 + el;
                int row = idxs[e], col = idxs[128 + e];
                float4 d   = *(float4*)&sD[el * DS + 4 * lane];
                uint2 haw  = *(const uint2*)(g_Ha16 + (size_t)row * HID + 4 * lane);
                uint2 hbw  = *(const uint2*)(g_Hb16 + (size_t)col * HID + 4 * lane);
                float4 b1v = *(const float4*)&b1s[4 * lane];
                float4 w2v = *(const float4*)&w2s[4 * lane];
                float ha0 = __uint_as_float(haw.x << 16);
                float ha1 = __uint_as_float(haw.x & 0xffff0000u);
                float ha2 = __uint_as_float(haw.y << 16);
                float ha3 = __uint_as_float(haw.y & 0xffff0000u);
                float hb0 = __uint_as_float(hbw.x << 16);
                float hb1 = __uint_as_float(hbw.x & 0xffff0000u);
                float hb2 = __uint_as_float(hbw.y << 16);
                float hb3 = __uint_as_float(hbw.y & 0xffff0000u);
                float partial =
                    elu(d.x + ha0 + hb0 + b1v.x) * w2v.x +
                    elu(d.y + ha1 + hb1 + b1v.y) * w2v.y +
                    elu(d.z + ha2 + hb2 + b1v.z) * w2v.z +
                    elu(d.w + ha3 + hb3 + b1v.w) * w2v.w;
#pragma unroll
                for (int off = 16; off; off >>= 1)
                    partial += __shfl_xor_sync(0xffffffffu, partial, off);
                // all lanes hold the full sum now
                float a = partial + b2v;
                float lg = a > 0.f ? a : 0.2f * a;
                if (lane == 0) g_a[tile * 128 + e] = lg;
                ls += __expf(lg);               // uniform across lanes, no divergence
            }
            __syncthreads();
        }
    }

    // ---- block-reduce exp-sum partials -> g_ps[blockIdx] ----
    float* red = (float*)idxs;
    if (lane == 0) red[wid] = ls;
    __syncthreads();
    if (tid == 0) {
        float S = 0.f;
#pragma unroll
        for (int w = 0; w < 8; w++) S += red[w];
        g_ps[blockIdx.x] = S;
    }
}

// ============================================================
// Kernel 3: final softmax reduction over GRID_E partials
// ============================================================
__global__ void softmax_final() {
    int t = threadIdx.x;
    __shared__ float ss_[512];
    ss_[t] = (t < GRID_E) ? g_ps[t] : 0.f;
    __syncthreads();
    for (int off = 256; off; off >>= 1) {
        if (t < off) ss_[t] += ss_[t + off];
        __syncthreads();
    }
    if (t == 0) { g_stats[0] = 0.f; g_stats[1] = 1.f / ss_[0]; }
}

// ============================================================
// Kernel 4: scatter  out[row] += alpha_e * h[col]   (red.v4.f32)
// ============================================================
__global__ void __launch_bounds__(256) scatter(const float* __restrict__ h,
                                               float* __restrict__ out) {
    int gw = (blockIdx.x * 256 + threadIdx.x) >> 5;
    int l = threadIdx.x & 31;
    float m = g_stats[0], inv = g_stats[1];
    int e0 = gw * 4;
#pragma unroll
    for (int e = 0; e < 4; e++) {
        int ed = e0 + e;
        if (ed >= NEDGE) return;
        float alpha = __expf(g_a[ed] - m) * inv;
        int row = g_row[ed];
        int col = g_col[ed];
        float4 hv = *(const float4*)&h[(size_t)col * HID + 4 * l];
        float* dst = &out[(size_t)row * HID + 4 * l];
        asm volatile("red.global.add.v4.f32 [%0], {%1, %2, %3, %4};"
                     :: "l"(dst), "f"(alpha * hv.x), "f"(alpha * hv.y),
                        "f"(alpha * hv.z), "f"(alpha * hv.w)
                     : "memory");
    }
}

// ============================================================
extern "C" void kernel_launch(void* const* d_in, const int* in_sizes, int n_in,
                              void* d_out, int out_size) {
    const float* h  = (const float*)d_in[0];
    const void*  ei = (const void*)d_in[1];
    const float* ea = (const float*)d_in[2];
    const float* W1 = (const float*)d_in[3];
    const float* b1 = (const float*)d_in[4];
    const float* W2 = (const float*)d_in[5];
    const float* b2 = (const float*)d_in[6];
    float* out = (float*)d_out;

    cudaFuncSetAttribute(node_mma, cudaFuncAttributeMaxDynamicSharedMemorySize, 71680);
    cudaFuncSetAttribute(edge_mma, cudaFuncAttributeMaxDynamicSharedMemorySize, 76288);

    detect<<<1, 32>>>((const int*)ei);
    convert<<<(NEDGE + 255) / 256, 256>>>(ei);
    prep_afrag<<<8, 256>>>(W1);
    prep_wab<<<32, 256>>>(W1);
    node_mma<<<NTILEN, 256, 71680>>>(h);
    cudaMemsetAsync(d_out, 0, (size_t)out_size * sizeof(float));
    edge_mma<<<GRID_E, 256, 76288>>>(ea, b1, W2, b2);
    softmax_final<<<1, 512>>>();
    scatter<<<25000, 256>>>(h, out);
}